// round 14
// baseline (speedup 1.0000x reference)
#include <cuda_runtime.h>
#include <math.h>
#include <stdint.h>

#define M_ROWS 8192
#define DMODEL 1024
#define DINNER 4096
#define LSEQ   1024
#define NHEAD  16

__device__ float g_Q  [M_ROWS*DMODEL];
__device__ float g_K  [M_ROWS*DMODEL];
__device__ float g_V  [M_ROWS*DMODEL];
__device__ float g_AO [M_ROWS*DMODEL];
__device__ float g_T0 [M_ROWS*DMODEL];
__device__ float g_X1 [M_ROWS*DMODEL];
__device__ float g_X1R[M_ROWS*DMODEL];
__device__ float g_H  [M_ROWS*DINNER];
__device__ float g_qr [M_ROWS*DMODEL];
__device__ float g_kr [M_ROWS*DMODEL];
__device__ float g_vr [M_ROWS*DMODEL];
__device__ float g_WQR[DMODEL*DMODEL];   // transposed [N,K], rna-rounded
__device__ float g_WKR[DMODEL*DMODEL];
__device__ float g_WVR[DMODEL*DMODEL];
__device__ float g_WFR[DMODEL*DMODEL];
__device__ float g_W1R[DMODEL*DINNER];
__device__ float g_W2R[DINNER*DMODEL];

__device__ __forceinline__ float tf32r(float x) {
    uint32_t u;
    asm("cvt.rna.tf32.f32 %0, %1;" : "=r"(u) : "f"(x));
    return __uint_as_float(u);
}

// fast exp on fma/alu pipes (no MUFU). valid for x <= ~0; deg-5, err ~2e-6.
__device__ __forceinline__ float fexp(float x) {
    float y = x * 1.4426950408889634f;
    float n = rintf(y);
    float f = y - n;
    float p = 1.3333558e-3f;
    p = fmaf(p, f, 9.6181291e-3f);
    p = fmaf(p, f, 5.5504109e-2f);
    p = fmaf(p, f, 2.4022651e-1f);
    p = fmaf(p, f, 6.9314718e-1f);
    p = fmaf(p, f, 1.0f);
    n = fmaxf(n, -126.f);
    float s = __int_as_float(((int)n + 127) << 23);
    return p * s;
}

#define MMA_TF32(ac, a0,a1,a2,a3, b0,b1)                                      \
    asm volatile(                                                             \
        "mma.sync.aligned.m16n8k8.row.col.f32.tf32.tf32.f32 "                 \
        "{%0,%1,%2,%3}, {%4,%5,%6,%7}, {%8,%9}, {%0,%1,%2,%3};"               \
        : "+f"(ac[0]), "+f"(ac[1]), "+f"(ac[2]), "+f"(ac[3])                  \
        : "r"(a0), "r"(a1), "r"(a2), "r"(a3), "r"(b0), "r"(b1))

#define LDSM_X4(r0,r1,r2,r3, ptr)                                             \
    asm volatile("ldmatrix.sync.aligned.m8n8.x4.shared.b16 {%0,%1,%2,%3}, [%4];" \
                 : "=r"(r0), "=r"(r1), "=r"(r2), "=r"(r3)                     \
                 : "r"((uint32_t)__cvta_generic_to_shared(ptr)))

__device__ __forceinline__ void cpa16(uint32_t smem, const void* gmem) {
    asm volatile("cp.async.cg.shared.global [%0], [%1], 16;\n" :: "r"(smem), "l"(gmem));
}
__device__ __forceinline__ void cpa_commit() {
    asm volatile("cp.async.commit_group;\n" ::);
}
template<int N>
__device__ __forceinline__ void cpa_wait() {
    asm volatile("cp.async.wait_group %0;\n" :: "n"(N));
}
__device__ __forceinline__ uint32_t smem_u32(const void* p) {
    return (uint32_t)__cvta_generic_to_shared(p);
}

// ---------------------------------------------------------------------------
// rna-round copy (float4)
// ---------------------------------------------------------------------------
__global__ void round_kernel(const float* __restrict__ X, float* __restrict__ Y, int n4)
{
    int i = blockIdx.x * blockDim.x + threadIdx.x;
    if (i < n4) {
        float4 v = ((const float4*)X)[i];
        float4 o;
        o.x = tf32r(v.x); o.y = tf32r(v.y); o.z = tf32r(v.z); o.w = tf32r(v.w);
        ((float4*)Y)[i] = o;
    }
}

// ---------------------------------------------------------------------------
// transpose + rna round: WT[n*K + k] = rna(W[k*N + n]).  block (32,8)
// ---------------------------------------------------------------------------
__global__ void transpose_round(const float* __restrict__ W, float* __restrict__ WT,
                                int K, int N)
{
    __shared__ float t[32][33];
    const int kb = blockIdx.y * 32, nb = blockIdx.x * 32;
    const int tx = threadIdx.x, ty = threadIdx.y;
    #pragma unroll
    for (int i = 0; i < 4; i++)
        t[ty + i * 8][tx] = W[(size_t)(kb + ty + i * 8) * N + nb + tx];
    __syncthreads();
    #pragma unroll
    for (int i = 0; i < 4; i++)
        WT[(size_t)(nb + ty + i * 8) * K + kb + tx] = tf32r(t[tx][ty + i * 8]);
}

// ---------------------------------------------------------------------------
// TF32 mma.sync GEMM, both operands K-major + ldmatrix fragments.
// C[M,N] = A[M,K] @ WT[N,K]^T + bias (+res)(relu?)(rnd?)
// Block 128x128, K-tile 16, 256 thr (8 warps 4x2), warp 32x64, 4-stage cp.async.
// Stage layout per operand: [128 rows][20 floats] (16 data + 4 pad).
// ---------------------------------------------------------------------------
#define OPS 20
#define STGF (128 * OPS)
#define GSTAGES 4
#define GSMEM (GSTAGES * 2 * STGF * 4)   // 81920 bytes

__global__ __launch_bounds__(256, 2)
void gemm_mma(const float* __restrict__ A, const float* __restrict__ WT,
              const float* __restrict__ bias, const float* __restrict__ res,
              float* __restrict__ C, int N, int K, int relu, int rnd)
{
    extern __shared__ __align__(16) float gsm[];
    float* Asm = gsm;                     // [GSTAGES][STGF]
    float* Bsm = gsm + GSTAGES * STGF;

    const int tid  = threadIdx.x;
    const int lane = tid & 31;
    const int warp = tid >> 5;
    const int m0 = (warp & 3) * 32, n0 = (warp >> 2) * 64;
    const int bm = blockIdx.y * 128, bn = blockIdx.x * 128;

    // cp.async mapping: thread -> row (0..127), two 16B granules
    const int rowg = tid >> 1;
    const int gb   = (tid & 1) * 2;       // granules gb, gb+1
    const float* Ap = A  + (size_t)(bm + rowg) * K + gb * 4;
    const float* Bp = WT + (size_t)(bn + rowg) * K + gb * 4;
    const uint32_t asb = smem_u32(Asm) + rowg * (OPS * 4) + gb * 16;
    const uint32_t bsb = smem_u32(Bsm) + rowg * (OPS * 4) + gb * 16;

    const int NT = K >> 4;

    // prologue: stages 0..2
    #pragma unroll
    for (int s = 0; s < GSTAGES - 1; s++) {
        const int kk = s << 4;
        cpa16(asb + s * (STGF * 4),      Ap + kk);
        cpa16(asb + s * (STGF * 4) + 16, Ap + kk + 4);
        cpa16(bsb + s * (STGF * 4),      Bp + kk);
        cpa16(bsb + s * (STGF * 4) + 16, Bp + kk + 4);
        cpa_commit();
    }
    cpa_wait<GSTAGES - 2>();
    __syncthreads();

    // ldmatrix lane addressing
    const int g  = lane >> 3;
    const int rf = ((g & 1) << 3) + (lane & 7);
    const int cf = (g >> 1) << 2;

    float acc[2][8][4];
    #pragma unroll
    for (int mt = 0; mt < 2; mt++)
        #pragma unroll
        for (int j = 0; j < 8; j++)
            #pragma unroll
            for (int e = 0; e < 4; e++) acc[mt][j][e] = 0.f;

    for (int kt = 0; kt < NT; kt++) {
        const int cur = kt & (GSTAGES - 1);
        const int ktn = kt + GSTAGES - 1;
        if (ktn < NT) {
            const int sn = ktn & (GSTAGES - 1);
            const int kk = ktn << 4;
            cpa16(asb + sn * (STGF * 4),      Ap + kk);
            cpa16(asb + sn * (STGF * 4) + 16, Ap + kk + 4);
            cpa16(bsb + sn * (STGF * 4),      Bp + kk);
            cpa16(bsb + sn * (STGF * 4) + 16, Bp + kk + 4);
        }
        cpa_commit();

        const float* as = Asm + cur * STGF;
        const float* bs = Bsm + cur * STGF;

        #pragma unroll
        for (int ks = 0; ks < 2; ks++) {
            const int k0 = ks << 3;
            uint32_t afr[2][4];
            #pragma unroll
            for (int mt = 0; mt < 2; mt++)
                LDSM_X4(afr[mt][0], afr[mt][1], afr[mt][2], afr[mt][3],
                        as + (m0 + mt * 16 + rf) * OPS + k0 + cf);
            #pragma unroll
            for (int jj = 0; jj < 4; jj++) {
                uint32_t b0e, b0o, b1e, b1o;
                LDSM_X4(b0e, b0o, b1e, b1o,
                        bs + (n0 + jj * 16 + rf) * OPS + k0 + cf);
                #pragma unroll
                for (int mt = 0; mt < 2; mt++) {
                    MMA_TF32(acc[mt][2*jj],   afr[mt][0], afr[mt][1], afr[mt][2], afr[mt][3], b0e, b1e);
                    MMA_TF32(acc[mt][2*jj+1], afr[mt][0], afr[mt][1], afr[mt][2], afr[mt][3], b0o, b1o);
                }
            }
        }

        cpa_wait<GSTAGES - 2>();
        __syncthreads();
    }

    // epilogue: C fragment c0,c1 -> (row, col..col+1); c2,c3 -> (row+8, ...)
    const int r_lane = lane >> 2;
    const int c_lane = (lane & 3) << 1;
    #pragma unroll
    for (int mt = 0; mt < 2; mt++) {
        const int row0 = bm + m0 + mt * 16 + r_lane;
        #pragma unroll
        for (int j = 0; j < 8; j++) {
            const int col = bn + n0 + j * 8 + c_lane;
            float2 bb = *(const float2*)(bias + col);
            float2 v0, v1;
            v0.x = acc[mt][j][0] + bb.x; v0.y = acc[mt][j][1] + bb.y;
            v1.x = acc[mt][j][2] + bb.x; v1.y = acc[mt][j][3] + bb.y;
            if (res) {
                float2 r0 = *(const float2*)(res + (size_t)row0 * N + col);
                float2 r1 = *(const float2*)(res + (size_t)(row0 + 8) * N + col);
                v0.x += r0.x; v0.y += r0.y;
                v1.x += r1.x; v1.y += r1.y;
            }
            if (relu) {
                v0.x = fmaxf(v0.x, 0.f); v0.y = fmaxf(v0.y, 0.f);
                v1.x = fmaxf(v1.x, 0.f); v1.y = fmaxf(v1.y, 0.f);
            }
            if (rnd) {
                v0.x = tf32r(v0.x); v0.y = tf32r(v0.y);
                v1.x = tf32r(v1.x); v1.y = tf32r(v1.y);
            }
            *(float2*)(C + (size_t)row0 * N + col) = v0;
            *(float2*)(C + (size_t)(row0 + 8) * N + col) = v1;
        }
    }
}

// ---------------------------------------------------------------------------
// MMA relative attention (measured good in R11 — unchanged)
// ---------------------------------------------------------------------------
#define ATTN_SMEM (22208 * 4)

__global__ __launch_bounds__(256)
void attn_mma(const float* __restrict__ Q, const float* __restrict__ Km,
              const float* __restrict__ Vm, const float* __restrict__ relk,
              const float* __restrict__ relv, float* __restrict__ O)
{
    extern __shared__ float sm[];
    float* Qs  = sm;            // [64][68]
    float* Ks  = sm + 4352;     // [64][68]
    float* Vs  = sm + 8704;     // [64][72]
    float* Ps  = sm + 13312;    // [64][68]
    float* Sq  = sm + 17664;    // [64][33]
    float* Tac = sm + 19776;    // [64][33]
    float* mrow= sm + 21888;    // [64]
    float* lrow= sm + 21952;    // [64]
    float* crow= sm + 22016;    // [64]
    float* red = sm + 22080;    // [64][2]
    float* Rk  = Ps;
    float* Rv  = Ks;

    const int tid  = threadIdx.x;
    const int lane = tid & 31, warp = tid >> 5;
    const int m0   = (warp & 3) * 16;
    const int n0h  = (warp >> 2) * 32;
    const int wh   = warp >> 2;
    const int lr = lane >> 2, lc = lane & 3;
    const int b = blockIdx.z, h = blockIdx.y;
    const int q0 = blockIdx.x << 6;

    for (int i = tid; i < 1024; i += 256) {
        int r = i >> 4, c = (i & 15) << 2;
        float4 v = *(const float4*)(Q + (size_t)(b*LSEQ + q0 + r)*DMODEL + h*64 + c);
        Qs[r*68+c]   = tf32r(v.x); Qs[r*68+c+1] = tf32r(v.y);
        Qs[r*68+c+2] = tf32r(v.z); Qs[r*68+c+3] = tf32r(v.w);
    }
    for (int i = tid; i < 2112; i += 256) { Rk[i] = relk[i]; Tac[i] = 0.f; }
    if (tid < 64) { mrow[tid] = -1e30f; lrow[tid] = 0.f; }
    __syncthreads();

    for (int i = tid; i < 2112; i += 256) {
        int qq = i / 33, r = i - qq*33;
        float s = 0.f;
        #pragma unroll 8
        for (int d = 0; d < 64; d++) s += Qs[qq*68 + d] * Rk[r*64 + d];
        Sq[i] = s * 0.125f;
    }

    float oacc[4][4];
    #pragma unroll
    for (int j = 0; j < 4; j++)
        #pragma unroll
        for (int e = 0; e < 4; e++) oacc[j][e] = 0.f;

    const int rowA = m0 + lr, rowB = rowA + 8;
    const int qgA = q0 + rowA, qgB = q0 + rowB;

    for (int kt = 0; kt < 16; kt++) {
        const int kbase = kt << 6;
        __syncthreads();
        for (int i = tid; i < 1024; i += 256) {
            int r = i >> 4, c = (i & 15) << 2;
            size_t go = (size_t)(b*LSEQ + kbase + r)*DMODEL + h*64 + c;
            float4 kv = *(const float4*)(Km + go);
            float4 vv = *(const float4*)(Vm + go);
            Ks[r*68+c]   = tf32r(kv.x); Ks[r*68+c+1] = tf32r(kv.y);
            Ks[r*68+c+2] = tf32r(kv.z); Ks[r*68+c+3] = tf32r(kv.w);
            Vs[r*72+c]   = tf32r(vv.x); Vs[r*72+c+1] = tf32r(vv.y);
            Vs[r*72+c+2] = tf32r(vv.z); Vs[r*72+c+3] = tf32r(vv.w);
        }
        __syncthreads();

        float sfr[4][4];
        #pragma unroll
        for (int j = 0; j < 4; j++)
            #pragma unroll
            for (int e = 0; e < 4; e++) sfr[j][e] = 0.f;

        const float* apq = Qs + (size_t)(m0 + lr)*68 + lc;
        #pragma unroll
        for (int ks = 0; ks < 8; ks++) {
            const int k0 = ks << 3;
            uint32_t a0 = __float_as_uint(apq[k0]);
            uint32_t a1 = __float_as_uint(apq[8*68 + k0]);
            uint32_t a2 = __float_as_uint(apq[k0 + 4]);
            uint32_t a3 = __float_as_uint(apq[8*68 + k0 + 4]);
            #pragma unroll
            for (int j = 0; j < 4; j++) {
                const float* bp = Ks + (size_t)(n0h + 8*j + lr)*68 + k0 + lc;
                uint32_t b0 = __float_as_uint(bp[0]);
                uint32_t b1 = __float_as_uint(bp[4]);
                MMA_TF32(sfr[j], a0, a1, a2, a3, b0, b1);
            }
        }

        float rmA = -1e30f, rmB = -1e30f;
        #pragma unroll
        for (int j = 0; j < 4; j++) {
            #pragma unroll
            for (int e = 0; e < 4; e++) {
                int col = n0h + 8*j + 2*lc + (e & 1);
                int kg = kbase + col;
                int row = (e < 2) ? rowA : rowB;
                int qg  = (e < 2) ? qgA : qgB;
                int d = kg - qg;
                int rb = d < -16 ? 0 : (d > 16 ? 32 : d + 16);
                float s = fmaf(sfr[j][e], 0.125f, Sq[row*33 + rb]);
                sfr[j][e] = s;
                if (e < 2) rmA = fmaxf(rmA, s); else rmB = fmaxf(rmB, s);
            }
        }
        rmA = fmaxf(rmA, __shfl_xor_sync(0xffffffffu, rmA, 1));
        rmA = fmaxf(rmA, __shfl_xor_sync(0xffffffffu, rmA, 2));
        rmB = fmaxf(rmB, __shfl_xor_sync(0xffffffffu, rmB, 1));
        rmB = fmaxf(rmB, __shfl_xor_sync(0xffffffffu, rmB, 2));
        if (lc == 0) { red[rowA*2 + wh] = rmA; red[rowB*2 + wh] = rmB; }
        __syncthreads();

        if (tid < 64) {
            float mo = mrow[tid];
            float mn = fmaxf(mo, fmaxf(red[tid*2], red[tid*2+1]));
            float c = fexp(mo - mn);
            mrow[tid] = mn; crow[tid] = c; lrow[tid] *= c;
            #pragma unroll
            for (int r = 0; r < 33; r++) Tac[tid*33 + r] *= c;
        }
        __syncthreads();

        const float mA = mrow[rowA], mB = mrow[rowB];
        float rsA = 0.f, rsB = 0.f, e0A = 0.f, e32A = 0.f, e0B = 0.f, e32B = 0.f;
        #pragma unroll
        for (int j = 0; j < 4; j++) {
            #pragma unroll
            for (int e = 0; e < 4; e++) {
                int col = n0h + 8*j + 2*lc + (e & 1);
                int kg = kbase + col;
                if (e < 2) {
                    float p = tf32r(fexp(sfr[j][e] - mA));
                    Ps[rowA*68 + col] = p;
                    rsA += p;
                    int d = kg - qgA;
                    if (d <= -16) e0A += p; else if (d >= 16) e32A += p;
                    else Tac[rowA*33 + d + 16] += p;
                } else {
                    float p = tf32r(fexp(sfr[j][e] - mB));
                    Ps[rowB*68 + col] = p;
                    rsB += p;
                    int d = kg - qgB;
                    if (d <= -16) e0B += p; else if (d >= 16) e32B += p;
                    else Tac[rowB*33 + d + 16] += p;
                }
            }
        }
        rsA  += __shfl_xor_sync(0xffffffffu, rsA, 1);  rsA  += __shfl_xor_sync(0xffffffffu, rsA, 2);
        rsB  += __shfl_xor_sync(0xffffffffu, rsB, 1);  rsB  += __shfl_xor_sync(0xffffffffu, rsB, 2);
        e0A  += __shfl_xor_sync(0xffffffffu, e0A, 1);  e0A  += __shfl_xor_sync(0xffffffffu, e0A, 2);
        e32A += __shfl_xor_sync(0xffffffffu, e32A, 1); e32A += __shfl_xor_sync(0xffffffffu, e32A, 2);
        e0B  += __shfl_xor_sync(0xffffffffu, e0B, 1);  e0B  += __shfl_xor_sync(0xffffffffu, e0B, 2);
        e32B += __shfl_xor_sync(0xffffffffu, e32B, 1); e32B += __shfl_xor_sync(0xffffffffu, e32B, 2);
        if (lc == 0) {
            red[rowA*2 + wh] = rsA;
            red[rowB*2 + wh] = rsB;
            if (e0A  != 0.f) atomicAdd(&Tac[rowA*33],      e0A);
            if (e32A != 0.f) atomicAdd(&Tac[rowA*33 + 32], e32A);
            if (e0B  != 0.f) atomicAdd(&Tac[rowB*33],      e0B);
            if (e32B != 0.f) atomicAdd(&Tac[rowB*33 + 32], e32B);
        }
        {
            float cA = crow[rowA], cB = crow[rowB];
            #pragma unroll
            for (int j = 0; j < 4; j++) {
                oacc[j][0] *= cA; oacc[j][1] *= cA;
                oacc[j][2] *= cB; oacc[j][3] *= cB;
            }
        }
        __syncthreads();

        const float* app = Ps + (size_t)(m0 + lr)*68 + lc;
        #pragma unroll
        for (int ks = 0; ks < 8; ks++) {
            const int k0 = ks << 3;
            uint32_t a0 = __float_as_uint(app[k0]);
            uint32_t a1 = __float_as_uint(app[8*68 + k0]);
            uint32_t a2 = __float_as_uint(app[k0 + 4]);
            uint32_t a3 = __float_as_uint(app[8*68 + k0 + 4]);
            #pragma unroll
            for (int j = 0; j < 4; j++) {
                const float* bp = Vs + (size_t)(k0 + lc)*72 + n0h + 8*j + lr;
                uint32_t b0 = __float_as_uint(bp[0]);
                uint32_t b1 = __float_as_uint(bp[4*72]);
                MMA_TF32(oacc[j], a0, a1, a2, a3, b0, b1);
            }
        }
        if (tid < 64) lrow[tid] += red[tid*2] + red[tid*2+1];
    }

    __syncthreads();
    for (int i = tid; i < 2112; i += 256) Rv[i] = relv[i];
    __syncthreads();

    float acc2[4][4];
    #pragma unroll
    for (int j = 0; j < 4; j++)
        #pragma unroll
        for (int e = 0; e < 4; e++) acc2[j][e] = 0.f;
    for (int r = 0; r < 33; r++) {
        float ta = Tac[rowA*33 + r], tb = Tac[rowB*33 + r];
        #pragma unroll
        for (int j = 0; j < 4; j++) {
            float rv0 = Rv[r*64 + n0h + 8*j + 2*lc];
            float rv1 = Rv[r*64 + n0h + 8*j + 2*lc + 1];
            acc2[j][0] = fmaf(ta, rv0, acc2[j][0]);
            acc2[j][1] = fmaf(ta, rv1, acc2[j][1]);
            acc2[j][2] = fmaf(tb, rv0, acc2[j][2]);
            acc2[j][3] = fmaf(tb, rv1, acc2[j][3]);
        }
    }
    float ilA = 1.f / lrow[rowA], ilB = 1.f / lrow[rowB];
    #pragma unroll
    for (int j = 0; j < 4; j++) {
        int col = n0h + 8*j + 2*lc;
        float2 o0, o1;
        o0.x = tf32r((oacc[j][0] + acc2[j][0]) * ilA);
        o0.y = tf32r((oacc[j][1] + acc2[j][1]) * ilA);
        o1.x = tf32r((oacc[j][2] + acc2[j][2]) * ilB);
        o1.y = tf32r((oacc[j][3] + acc2[j][3]) * ilB);
        *(float2*)(O + (size_t)(b*LSEQ + q0 + rowA)*DMODEL + h*64 + col) = o0;
        *(float2*)(O + (size_t)(b*LSEQ + q0 + rowB)*DMODEL + h*64 + col) = o1;
    }
}

// ---------------------------------------------------------------------------
// LayerNorm; optional rounded second output
// ---------------------------------------------------------------------------
__global__ void ln_kernel(const float* __restrict__ X, const float* __restrict__ g,
                          const float* __restrict__ bta, float* __restrict__ Y,
                          float* __restrict__ Yr)
{
    __shared__ float rs[18];
    const int row = blockIdx.x, tid = threadIdx.x;
    float4 v = ((const float4*)(X + (size_t)row * 1024))[tid];
    float s  = v.x + v.y + v.z + v.w;
    float s2 = v.x*v.x + v.y*v.y + v.z*v.z + v.w*v.w;
    #pragma unroll
    for (int o = 16; o > 0; o >>= 1) {
        s  += __shfl_down_sync(0xffffffffu, s, o);
        s2 += __shfl_down_sync(0xffffffffu, s2, o);
    }
    int wid = tid >> 5;
    if ((tid & 31) == 0) { rs[wid] = s; rs[8 + wid] = s2; }
    __syncthreads();
    if (tid == 0) {
        float ts = 0.f, ts2 = 0.f;
        for (int w = 0; w < 8; w++) { ts += rs[w]; ts2 += rs[8 + w]; }
        float mu = ts * (1.f / 1024.f);
        float var = ts2 * (1.f / 1024.f) - mu * mu;
        rs[16] = mu;
        rs[17] = rsqrtf(var + 1e-6f);
    }
    __syncthreads();
    float mu = rs[16], rstd = rs[17];
    float4 gg = ((const float4*)g)[tid];
    float4 bb = ((const float4*)bta)[tid];
    float4 o;
    o.x = (v.x - mu) * rstd * gg.x + bb.x;
    o.y = (v.y - mu) * rstd * gg.y + bb.y;
    o.z = (v.z - mu) * rstd * gg.z + bb.z;
    o.w = (v.w - mu) * rstd * gg.w + bb.w;
    ((float4*)(Y + (size_t)row * 1024))[tid] = o;
    if (Yr) {
        float4 r;
        r.x = tf32r(o.x); r.y = tf32r(o.y); r.z = tf32r(o.z); r.w = tf32r(o.w);
        ((float4*)(Yr + (size_t)row * 1024))[tid] = r;
    }
}

// ---------------------------------------------------------------------------
extern "C" void kernel_launch(void* const* d_in, const int* in_sizes, int n_in,
                              void* d_out, int out_size)
{
    const float* q    = (const float*)d_in[0];
    const float* k    = (const float*)d_in[1];
    const float* v    = (const float*)d_in[2];
    const float* wq   = (const float*)d_in[3];
    const float* bq   = (const float*)d_in[4];
    const float* wk   = (const float*)d_in[5];
    const float* bk   = (const float*)d_in[6];
    const float* wv   = (const float*)d_in[7];
    const float* bv   = (const float*)d_in[8];
    const float* wfc  = (const float*)d_in[9];
    const float* bfc  = (const float*)d_in[10];
    const float* w1   = (const float*)d_in[11];
    const float* b1   = (const float*)d_in[12];
    const float* w2   = (const float*)d_in[13];
    const float* b2   = (const float*)d_in[14];
    const float* lng  = (const float*)d_in[15];
    const float* lnb  = (const float*)d_in[16];
    const float* relk = (const float*)d_in[17];
    const float* relv = (const float*)d_in[18];
    float* out = (float*)d_out;

    float *Qp, *Kp, *Vp, *AOp, *T0p, *X1p, *X1Rp, *Hp;
    float *qr, *kr, *vr, *wqr, *wkr, *wvr, *wfr, *w1r, *w2r;
    cudaGetSymbolAddress((void**)&Qp,   g_Q);
    cudaGetSymbolAddress((void**)&Kp,   g_K);
    cudaGetSymbolAddress((void**)&Vp,   g_V);
    cudaGetSymbolAddress((void**)&AOp,  g_AO);
    cudaGetSymbolAddress((void**)&T0p,  g_T0);
    cudaGetSymbolAddress((void**)&X1p,  g_X1);
    cudaGetSymbolAddress((void**)&X1Rp, g_X1R);
    cudaGetSymbolAddress((void**)&Hp,   g_H);
    cudaGetSymbolAddress((void**)&qr,   g_qr);
    cudaGetSymbolAddress((void**)&kr,   g_kr);
    cudaGetSymbolAddress((void**)&vr,   g_vr);
    cudaGetSymbolAddress((void**)&wqr,  g_WQR);
    cudaGetSymbolAddress((void**)&wkr,  g_WKR);
    cudaGetSymbolAddress((void**)&wvr,  g_WVR);
    cudaGetSymbolAddress((void**)&wfr,  g_WFR);
    cudaGetSymbolAddress((void**)&w1r,  g_W1R);
    cudaGetSymbolAddress((void**)&w2r,  g_W2R);

    cudaFuncSetAttribute(attn_mma, cudaFuncAttributeMaxDynamicSharedMemorySize, ATTN_SMEM);
    cudaFuncSetAttribute(gemm_mma, cudaFuncAttributeMaxDynamicSharedMemorySize, GSMEM);

    // pre-pass: transpose+round weights to [N,K]; round activations (rna)
    dim3 tb(32, 8);
    transpose_round<<<dim3(1024/32, 1024/32), tb>>>(wq,  wqr, 1024, 1024);
    transpose_round<<<dim3(1024/32, 1024/32), tb>>>(wk,  wkr, 1024, 1024);
    transpose_round<<<dim3(1024/32, 1024/32), tb>>>(wv,  wvr, 1024, 1024);
    transpose_round<<<dim3(1024/32, 1024/32), tb>>>(wfc, wfr, 1024, 1024);
    transpose_round<<<dim3(4096/32, 1024/32), tb>>>(w1,  w1r, 1024, 4096);
    transpose_round<<<dim3(1024/32, 4096/32), tb>>>(w2,  w2r, 4096, 1024);
    const int MR = M_ROWS * DMODEL / 4;
    round_kernel<<<(MR + 255) / 256, 256>>>(q, qr, MR);
    round_kernel<<<(MR + 255) / 256, 256>>>(k, kr, MR);
    round_kernel<<<(MR + 255) / 256, 256>>>(v, vr, MR);

    dim3 blk(256);
    dim3 g1024(1024 / 128, 8192 / 128);
    dim3 g4096(4096 / 128, 8192 / 128);

    gemm_mma<<<g1024, blk, GSMEM>>>(qr, wqr, bq, nullptr, Qp, 1024, 1024, 0, 0);
    gemm_mma<<<g1024, blk, GSMEM>>>(kr, wkr, bk, nullptr, Kp, 1024, 1024, 0, 0);
    gemm_mma<<<g1024, blk, GSMEM>>>(vr, wvr, bv, nullptr, Vp, 1024, 1024, 0, 0);

    attn_mma<<<dim3(16, NHEAD, 8), blk, ATTN_SMEM>>>(Qp, Kp, Vp, relk, relv, AOp);

    gemm_mma<<<g1024, blk, GSMEM>>>(AOp, wfr, bfc, q, T0p, 1024, 1024, 0, 0);
    ln_kernel<<<8192, 256>>>(T0p, lng, lnb, X1p, X1Rp);

    gemm_mma<<<g4096, blk, GSMEM>>>(X1Rp, w1r, b1, nullptr, Hp, 4096, 1024, 1, 1);
    gemm_mma<<<g1024, blk, GSMEM>>>(Hp, w2r, b2, X1p, T0p, 1024, 4096, 0, 0);
    ln_kernel<<<8192, 256>>>(T0p, lng, lnb, out, nullptr);
}

// round 15
// speedup vs baseline: 1.3372x; 1.3372x over previous
#include <cuda_runtime.h>
#include <cuda_fp16.h>
#include <math.h>
#include <stdint.h>

#define M_ROWS 8192
#define DMODEL 1024
#define DINNER 4096
#define LSEQ   1024
#define NHEAD  16

// fp32 intermediates
__device__ float  g_Q  [M_ROWS*DMODEL];
__device__ float  g_K  [M_ROWS*DMODEL];
__device__ float  g_V  [M_ROWS*DMODEL];
__device__ float  g_T0 [M_ROWS*DMODEL];
__device__ float  g_X1 [M_ROWS*DMODEL];
// half operands
__device__ __half g_qh [M_ROWS*DMODEL];
__device__ __half g_kh [M_ROWS*DMODEL];
__device__ __half g_vh [M_ROWS*DMODEL];
__device__ __half g_AOh[M_ROWS*DMODEL];
__device__ __half g_X1h[M_ROWS*DMODEL];
__device__ __half g_Hh [M_ROWS*DINNER];
// tiled half weights: [nb][kt][128 rows x 32 halves] contiguous
__device__ __half g_WQH[DMODEL*DMODEL];
__device__ __half g_WKH[DMODEL*DMODEL];
__device__ __half g_WVH[DMODEL*DMODEL];
__device__ __half g_WFH[DMODEL*DMODEL];
__device__ __half g_W1H[DMODEL*DINNER];
__device__ __half g_W2H[DINNER*DMODEL];

__device__ __forceinline__ float tf32r(float x) {
    uint32_t u;
    asm("cvt.rna.tf32.f32 %0, %1;" : "=r"(u) : "f"(x));
    return __uint_as_float(u);
}

// fast exp on fma/alu pipes (no MUFU). deg-5, err ~2e-6.
__device__ __forceinline__ float fexp(float x) {
    float y = x * 1.4426950408889634f;
    float n = rintf(y);
    float f = y - n;
    float p = 1.3333558e-3f;
    p = fmaf(p, f, 9.6181291e-3f);
    p = fmaf(p, f, 5.5504109e-2f);
    p = fmaf(p, f, 2.4022651e-1f);
    p = fmaf(p, f, 6.9314718e-1f);
    p = fmaf(p, f, 1.0f);
    n = fmaxf(n, -126.f);
    float s = __int_as_float(((int)n + 127) << 23);
    return p * s;
}

#define MMA_TF32(ac, a0,a1,a2,a3, b0,b1)                                      \
    asm volatile(                                                             \
        "mma.sync.aligned.m16n8k8.row.col.f32.tf32.tf32.f32 "                 \
        "{%0,%1,%2,%3}, {%4,%5,%6,%7}, {%8,%9}, {%0,%1,%2,%3};"               \
        : "+f"(ac[0]), "+f"(ac[1]), "+f"(ac[2]), "+f"(ac[3])                  \
        : "r"(a0), "r"(a1), "r"(a2), "r"(a3), "r"(b0), "r"(b1))

#define MMA_F16(ac, a0,a1,a2,a3, b0,b1)                                       \
    asm volatile(                                                             \
        "mma.sync.aligned.m16n8k16.row.col.f32.f16.f16.f32 "                  \
        "{%0,%1,%2,%3}, {%4,%5,%6,%7}, {%8,%9}, {%0,%1,%2,%3};"               \
        : "+f"(ac[0]), "+f"(ac[1]), "+f"(ac[2]), "+f"(ac[3])                  \
        : "r"(a0), "r"(a1), "r"(a2), "r"(a3), "r"(b0), "r"(b1))

#define LDSM_X4(r0,r1,r2,r3, ptr)                                             \
    asm volatile("ldmatrix.sync.aligned.m8n8.x4.shared.b16 {%0,%1,%2,%3}, [%4];" \
                 : "=r"(r0), "=r"(r1), "=r"(r2), "=r"(r3)                     \
                 : "r"((uint32_t)__cvta_generic_to_shared(ptr)))

__device__ __forceinline__ void cpa16(uint32_t smem, const void* gmem) {
    asm volatile("cp.async.cg.shared.global [%0], [%1], 16;\n" :: "r"(smem), "l"(gmem));
}
__device__ __forceinline__ void cpa_commit() {
    asm volatile("cp.async.commit_group;\n" ::);
}
template<int N>
__device__ __forceinline__ void cpa_wait() {
    asm volatile("cp.async.wait_group %0;\n" :: "n"(N));
}
__device__ __forceinline__ uint32_t smem_u32(const void* p) {
    return (uint32_t)__cvta_generic_to_shared(p);
}

// ---------------------------------------------------------------------------
// fp32 -> fp16 copy (float4 -> 4 halves)
// ---------------------------------------------------------------------------
__global__ void tohalf(const float* __restrict__ X, __half* __restrict__ Y, int n4)
{
    int i = blockIdx.x * blockDim.x + threadIdx.x;
    if (i < n4) {
        float4 v = ((const float4*)X)[i];
        __half2 h0 = __floats2half2_rn(v.x, v.y);
        __half2 h1 = __floats2half2_rn(v.z, v.w);
        ((__half2*)Y)[2*i]   = h0;
        ((__half2*)Y)[2*i+1] = h1;
    }
}

// ---------------------------------------------------------------------------
// weight prep: W[K,N] fp32 -> tiled half Wt[nb][kt][128 rows][32 halves]
// block = one (nb, kt) tile; thread t: row t>>1, halves (t&1)*16..+15
// ---------------------------------------------------------------------------
__global__ void prep_weight(const float* __restrict__ W, __half* __restrict__ Wt,
                            int K, int N)
{
    const int nb = blockIdx.x, kt = blockIdx.y;
    const int nrow = threadIdx.x >> 1, kk0 = (threadIdx.x & 1) * 16;
    const float* src = W + (size_t)(kt * 32 + kk0) * N + nb * 128 + nrow;
    __half* dst = Wt + (((size_t)nb * (K >> 5) + kt) << 12) + nrow * 32 + kk0;
    #pragma unroll
    for (int i = 0; i < 16; i++)
        dst[i] = __float2half(src[(size_t)i * N]);
}

// ---------------------------------------------------------------------------
// fp16 mma.sync GEMM: C = A[M,K] @ Wt^T + bias (+res)(relu?)
// A half K-major; Wt tiled half. Block 128x128, K-chunk 32, 4-stage cp.async.
// Smem rows: 64B data + 16B pad (stride 80B) -> conflict-free ldmatrix.
// ---------------------------------------------------------------------------
#define HOPS 40                      // halves per smem row (80 B)
#define HSTG (128 * HOPS)            // halves per operand stage
#define GST 4
#define GSMEMB (GST * 2 * HSTG * 2)  // 81920 bytes

__global__ __launch_bounds__(256, 2)
void gemm_h(const __half* __restrict__ A, const __half* __restrict__ Wt,
            const float* __restrict__ bias, const float* __restrict__ res,
            float* __restrict__ Cf, __half* __restrict__ Ch,
            int N, int K, int relu)
{
    extern __shared__ __align__(16) __half hsm[];
    __half* Asm = hsm;
    __half* Bsm = hsm + GST * HSTG;

    const int tid = threadIdx.x, lane = tid & 31, warp = tid >> 5;
    const int m0 = (warp & 3) * 32, n0 = (warp >> 2) * 64;
    const int bm = blockIdx.y * 128, bn = blockIdx.x * 128;

    // cp.async mapping: thread -> row tid>>1, halves (tid&1)*16..+15 (32B)
    const int rowg = tid >> 1;
    const int hb = (tid & 1) * 16;
    const __half* Ap = A + (size_t)(bm + rowg) * K + hb;
    const __half* Bp = Wt + (((size_t)blockIdx.x * (K >> 5)) << 12)
                          + (size_t)rowg * 32 + hb;
    const uint32_t asb = smem_u32(Asm) + rowg * 80 + hb * 2;
    const uint32_t bsb = smem_u32(Bsm) + rowg * 80 + hb * 2;

    const int NT = K >> 5;

    #pragma unroll
    for (int s = 0; s < GST - 1; s++) {
        cpa16(asb + s * (HSTG * 2),      Ap + s * 32);
        cpa16(asb + s * (HSTG * 2) + 16, Ap + s * 32 + 8);
        cpa16(bsb + s * (HSTG * 2),      Bp + ((size_t)s << 12));
        cpa16(bsb + s * (HSTG * 2) + 16, Bp + ((size_t)s << 12) + 8);
        cpa_commit();
    }
    cpa_wait<GST - 2>();
    __syncthreads();

    // ldmatrix lane addressing (4 matrices: rows 0-7/8-15 x 16B chunks 0/1)
    const int rf = (((lane >> 3) & 1) << 3) + (lane & 7);
    const int cq = (lane >> 4) * 8;      // halves

    float acc[2][8][4];
    #pragma unroll
    for (int mt = 0; mt < 2; mt++)
        #pragma unroll
        for (int j = 0; j < 8; j++)
            #pragma unroll
            for (int e = 0; e < 4; e++) acc[mt][j][e] = 0.f;

    for (int kt = 0; kt < NT; kt++) {
        const int cur = kt & (GST - 1);
        const int ktn = kt + GST - 1;
        if (ktn < NT) {
            const int sn = ktn & (GST - 1);
            cpa16(asb + sn * (HSTG * 2),      Ap + (size_t)ktn * 32);
            cpa16(asb + sn * (HSTG * 2) + 16, Ap + (size_t)ktn * 32 + 8);
            cpa16(bsb + sn * (HSTG * 2),      Bp + ((size_t)ktn << 12));
            cpa16(bsb + sn * (HSTG * 2) + 16, Bp + ((size_t)ktn << 12) + 8);
        }
        cpa_commit();

        const __half* as = Asm + cur * HSTG;
        const __half* bs = Bsm + cur * HSTG;

        #pragma unroll
        for (int s = 0; s < 2; s++) {     // two k16 steps per 32-chunk
            const int kh = s * 16;
            uint32_t af[2][4];
            #pragma unroll
            for (int mt = 0; mt < 2; mt++)
                LDSM_X4(af[mt][0], af[mt][1], af[mt][2], af[mt][3],
                        as + (m0 + mt * 16 + rf) * HOPS + kh + cq);
            #pragma unroll
            for (int jj = 0; jj < 4; jj++) {
                uint32_t b0, b1, b2, b3;
                LDSM_X4(b0, b1, b2, b3,
                        bs + (n0 + jj * 16 + rf) * HOPS + kh + cq);
                #pragma unroll
                for (int mt = 0; mt < 2; mt++) {
                    MMA_F16(acc[mt][2*jj],   af[mt][0], af[mt][1], af[mt][2], af[mt][3], b0, b2);
                    MMA_F16(acc[mt][2*jj+1], af[mt][0], af[mt][1], af[mt][2], af[mt][3], b1, b3);
                }
            }
        }

        cpa_wait<GST - 2>();
        __syncthreads();
    }

    // epilogue
    const int r_lane = lane >> 2;
    const int c_lane = (lane & 3) << 1;
    #pragma unroll
    for (int mt = 0; mt < 2; mt++) {
        const int row0 = bm + m0 + mt * 16 + r_lane;
        #pragma unroll
        for (int j = 0; j < 8; j++) {
            const int col = bn + n0 + j * 8 + c_lane;
            float2 bb = *(const float2*)(bias + col);
            float2 v0, v1;
            v0.x = acc[mt][j][0] + bb.x; v0.y = acc[mt][j][1] + bb.y;
            v1.x = acc[mt][j][2] + bb.x; v1.y = acc[mt][j][3] + bb.y;
            if (res) {
                float2 r0 = *(const float2*)(res + (size_t)row0 * N + col);
                float2 r1 = *(const float2*)(res + (size_t)(row0 + 8) * N + col);
                v0.x += r0.x; v0.y += r0.y;
                v1.x += r1.x; v1.y += r1.y;
            }
            if (relu) {
                v0.x = fmaxf(v0.x, 0.f); v0.y = fmaxf(v0.y, 0.f);
                v1.x = fmaxf(v1.x, 0.f); v1.y = fmaxf(v1.y, 0.f);
            }
            if (Cf) {
                *(float2*)(Cf + (size_t)row0 * N + col) = v0;
                *(float2*)(Cf + (size_t)(row0 + 8) * N + col) = v1;
            }
            if (Ch) {
                *(__half2*)(Ch + (size_t)row0 * N + col) = __floats2half2_rn(v0.x, v0.y);
                *(__half2*)(Ch + (size_t)(row0 + 8) * N + col) = __floats2half2_rn(v1.x, v1.y);
            }
        }
    }
}

// ---------------------------------------------------------------------------
// MMA relative attention (R11-proven). Output now half (for fc GEMM operand).
// ---------------------------------------------------------------------------
#define ATTN_SMEM (22208 * 4)

__global__ __launch_bounds__(256)
void attn_mma(const float* __restrict__ Q, const float* __restrict__ Km,
              const float* __restrict__ Vm, const float* __restrict__ relk,
              const float* __restrict__ relv, __half* __restrict__ O)
{
    extern __shared__ float sm[];
    float* Qs  = sm;            // [64][68]
    float* Ks  = sm + 4352;     // [64][68]
    float* Vs  = sm + 8704;     // [64][72]
    float* Ps  = sm + 13312;    // [64][68]
    float* Sq  = sm + 17664;    // [64][33]
    float* Tac = sm + 19776;    // [64][33]
    float* mrow= sm + 21888;    // [64]
    float* lrow= sm + 21952;    // [64]
    float* crow= sm + 22016;    // [64]
    float* red = sm + 22080;    // [64][2]
    float* Rk  = Ps;
    float* Rv  = Ks;

    const int tid  = threadIdx.x;
    const int lane = tid & 31, warp = tid >> 5;
    const int m0   = (warp & 3) * 16;
    const int n0h  = (warp >> 2) * 32;
    const int wh   = warp >> 2;
    const int lr = lane >> 2, lc = lane & 3;
    const int b = blockIdx.z, h = blockIdx.y;
    const int q0 = blockIdx.x << 6;

    for (int i = tid; i < 1024; i += 256) {
        int r = i >> 4, c = (i & 15) << 2;
        float4 v = *(const float4*)(Q + (size_t)(b*LSEQ + q0 + r)*DMODEL + h*64 + c);
        Qs[r*68+c]   = tf32r(v.x); Qs[r*68+c+1] = tf32r(v.y);
        Qs[r*68+c+2] = tf32r(v.z); Qs[r*68+c+3] = tf32r(v.w);
    }
    for (int i = tid; i < 2112; i += 256) { Rk[i] = relk[i]; Tac[i] = 0.f; }
    if (tid < 64) { mrow[tid] = -1e30f; lrow[tid] = 0.f; }
    __syncthreads();

    for (int i = tid; i < 2112; i += 256) {
        int qq = i / 33, r = i - qq*33;
        float s = 0.f;
        #pragma unroll 8
        for (int d = 0; d < 64; d++) s += Qs[qq*68 + d] * Rk[r*64 + d];
        Sq[i] = s * 0.125f;
    }

    float oacc[4][4];
    #pragma unroll
    for (int j = 0; j < 4; j++)
        #pragma unroll
        for (int e = 0; e < 4; e++) oacc[j][e] = 0.f;

    const int rowA = m0 + lr, rowB = rowA + 8;
    const int qgA = q0 + rowA, qgB = q0 + rowB;

    for (int kt = 0; kt < 16; kt++) {
        const int kbase = kt << 6;
        __syncthreads();
        for (int i = tid; i < 1024; i += 256) {
            int r = i >> 4, c = (i & 15) << 2;
            size_t go = (size_t)(b*LSEQ + kbase + r)*DMODEL + h*64 + c;
            float4 kv = *(const float4*)(Km + go);
            float4 vv = *(const float4*)(Vm + go);
            Ks[r*68+c]   = tf32r(kv.x); Ks[r*68+c+1] = tf32r(kv.y);
            Ks[r*68+c+2] = tf32r(kv.z); Ks[r*68+c+3] = tf32r(kv.w);
            Vs[r*72+c]   = tf32r(vv.x); Vs[r*72+c+1] = tf32r(vv.y);
            Vs[r*72+c+2] = tf32r(vv.z); Vs[r*72+c+3] = tf32r(vv.w);
        }
        __syncthreads();

        float sfr[4][4];
        #pragma unroll
        for (int j = 0; j < 4; j++)
            #pragma unroll
            for (int e = 0; e < 4; e++) sfr[j][e] = 0.f;

        const float* apq = Qs + (size_t)(m0 + lr)*68 + lc;
        #pragma unroll
        for (int ks = 0; ks < 8; ks++) {
            const int k0 = ks << 3;
            uint32_t a0 = __float_as_uint(apq[k0]);
            uint32_t a1 = __float_as_uint(apq[8*68 + k0]);
            uint32_t a2 = __float_as_uint(apq[k0 + 4]);
            uint32_t a3 = __float_as_uint(apq[8*68 + k0 + 4]);
            #pragma unroll
            for (int j = 0; j < 4; j++) {
                const float* bp = Ks + (size_t)(n0h + 8*j + lr)*68 + k0 + lc;
                uint32_t b0 = __float_as_uint(bp[0]);
                uint32_t b1 = __float_as_uint(bp[4]);
                MMA_TF32(sfr[j], a0, a1, a2, a3, b0, b1);
            }
        }

        float rmA = -1e30f, rmB = -1e30f;
        #pragma unroll
        for (int j = 0; j < 4; j++) {
            #pragma unroll
            for (int e = 0; e < 4; e++) {
                int col = n0h + 8*j + 2*lc + (e & 1);
                int kg = kbase + col;
                int row = (e < 2) ? rowA : rowB;
                int qg  = (e < 2) ? qgA : qgB;
                int d = kg - qg;
                int rb = d < -16 ? 0 : (d > 16 ? 32 : d + 16);
                float s = fmaf(sfr[j][e], 0.125f, Sq[row*33 + rb]);
                sfr[j][e] = s;
                if (e < 2) rmA = fmaxf(rmA, s); else rmB = fmaxf(rmB, s);
            }
        }
        rmA = fmaxf(rmA, __shfl_xor_sync(0xffffffffu, rmA, 1));
        rmA = fmaxf(rmA, __shfl_xor_sync(0xffffffffu, rmA, 2));
        rmB = fmaxf(rmB, __shfl_xor_sync(0xffffffffu, rmB, 1));
        rmB = fmaxf(rmB, __shfl_xor_sync(0xffffffffu, rmB, 2));
        if (lc == 0) { red[rowA*2 + wh] = rmA; red[rowB*2 + wh] = rmB; }
        __syncthreads();

        if (tid < 64) {
            float mo = mrow[tid];
            float mn = fmaxf(mo, fmaxf(red[tid*2], red[tid*2+1]));
            float c = fexp(mo - mn);
            mrow[tid] = mn; crow[tid] = c; lrow[tid] *= c;
            #pragma unroll
            for (int r = 0; r < 33; r++) Tac[tid*33 + r] *= c;
        }
        __syncthreads();

        const float mA = mrow[rowA], mB = mrow[rowB];
        float rsA = 0.f, rsB = 0.f, e0A = 0.f, e32A = 0.f, e0B = 0.f, e32B = 0.f;
        #pragma unroll
        for (int j = 0; j < 4; j++) {
            #pragma unroll
            for (int e = 0; e < 4; e++) {
                int col = n0h + 8*j + 2*lc + (e & 1);
                int kg = kbase + col;
                if (e < 2) {
                    float p = tf32r(fexp(sfr[j][e] - mA));
                    Ps[rowA*68 + col] = p;
                    rsA += p;
                    int d = kg - qgA;
                    if (d <= -16) e0A += p; else if (d >= 16) e32A += p;
                    else Tac[rowA*33 + d + 16] += p;
                } else {
                    float p = tf32r(fexp(sfr[j][e] - mB));
                    Ps[rowB*68 + col] = p;
                    rsB += p;
                    int d = kg - qgB;
                    if (d <= -16) e0B += p; else if (d >= 16) e32B += p;
                    else Tac[rowB*33 + d + 16] += p;
                }
            }
        }
        rsA  += __shfl_xor_sync(0xffffffffu, rsA, 1);  rsA  += __shfl_xor_sync(0xffffffffu, rsA, 2);
        rsB  += __shfl_xor_sync(0xffffffffu, rsB, 1);  rsB  += __shfl_xor_sync(0xffffffffu, rsB, 2);
        e0A  += __shfl_xor_sync(0xffffffffu, e0A, 1);  e0A  += __shfl_xor_sync(0xffffffffu, e0A, 2);
        e32A += __shfl_xor_sync(0xffffffffu, e32A, 1); e32A += __shfl_xor_sync(0xffffffffu, e32A, 2);
        e0B  += __shfl_xor_sync(0xffffffffu, e0B, 1);  e0B  += __shfl_xor_sync(0xffffffffu, e0B, 2);
        e32B += __shfl_xor_sync(0xffffffffu, e32B, 1); e32B += __shfl_xor_sync(0xffffffffu, e32B, 2);
        if (lc == 0) {
            red[rowA*2 + wh] = rsA;
            red[rowB*2 + wh] = rsB;
            if (e0A  != 0.f) atomicAdd(&Tac[rowA*33],      e0A);
            if (e32A != 0.f) atomicAdd(&Tac[rowA*33 + 32], e32A);
            if (e0B  != 0.f) atomicAdd(&Tac[rowB*33],      e0B);
            if (e32B != 0.f) atomicAdd(&Tac[rowB*33 + 32], e32B);
        }
        {
            float cA = crow[rowA], cB = crow[rowB];
            #pragma unroll
            for (int j = 0; j < 4; j++) {
                oacc[j][0] *= cA; oacc[j][1] *= cA;
                oacc[j][2] *= cB; oacc[j][3] *= cB;
            }
        }
        __syncthreads();

        const float* app = Ps + (size_t)(m0 + lr)*68 + lc;
        #pragma unroll
        for (int ks = 0; ks < 8; ks++) {
            const int k0 = ks << 3;
            uint32_t a0 = __float_as_uint(app[k0]);
            uint32_t a1 = __float_as_uint(app[8*68 + k0]);
            uint32_t a2 = __float_as_uint(app[k0 + 4]);
            uint32_t a3 = __float_as_uint(app[8*68 + k0 + 4]);
            #pragma unroll
            for (int j = 0; j < 4; j++) {
                const float* bp = Vs + (size_t)(k0 + lc)*72 + n0h + 8*j + lr;
                uint32_t b0 = __float_as_uint(bp[0]);
                uint32_t b1 = __float_as_uint(bp[4*72]);
                MMA_TF32(oacc[j], a0, a1, a2, a3, b0, b1);
            }
        }
        if (tid < 64) lrow[tid] += red[tid*2] + red[tid*2+1];
    }

    __syncthreads();
    for (int i = tid; i < 2112; i += 256) Rv[i] = relv[i];
    __syncthreads();

    float acc2[4][4];
    #pragma unroll
    for (int j = 0; j < 4; j++)
        #pragma unroll
        for (int e = 0; e < 4; e++) acc2[j][e] = 0.f;
    for (int r = 0; r < 33; r++) {
        float ta = Tac[rowA*33 + r], tb = Tac[rowB*33 + r];
        #pragma unroll
        for (int j = 0; j < 4; j++) {
            float rv0 = Rv[r*64 + n0h + 8*j + 2*lc];
            float rv1 = Rv[r*64 + n0h + 8*j + 2*lc + 1];
            acc2[j][0] = fmaf(ta, rv0, acc2[j][0]);
            acc2[j][1] = fmaf(ta, rv1, acc2[j][1]);
            acc2[j][2] = fmaf(tb, rv0, acc2[j][2]);
            acc2[j][3] = fmaf(tb, rv1, acc2[j][3]);
        }
    }
    float ilA = 1.f / lrow[rowA], ilB = 1.f / lrow[rowB];
    #pragma unroll
    for (int j = 0; j < 4; j++) {
        int col = n0h + 8*j + 2*lc;
        __half2 h0 = __floats2half2_rn((oacc[j][0] + acc2[j][0]) * ilA,
                                       (oacc[j][1] + acc2[j][1]) * ilA);
        __half2 h1 = __floats2half2_rn((oacc[j][2] + acc2[j][2]) * ilB,
                                       (oacc[j][3] + acc2[j][3]) * ilB);
        *(__half2*)(O + (size_t)(b*LSEQ + q0 + rowA)*DMODEL + h*64 + col) = h0;
        *(__half2*)(O + (size_t)(b*LSEQ + q0 + rowB)*DMODEL + h*64 + col) = h1;
    }
}

// ---------------------------------------------------------------------------
// LayerNorm; optional half second output (next GEMM's A operand)
// ---------------------------------------------------------------------------
__global__ void ln_kernel(const float* __restrict__ X, const float* __restrict__ g,
                          const float* __restrict__ bta, float* __restrict__ Y,
                          __half* __restrict__ Yh)
{
    __shared__ float rs[18];
    const int row = blockIdx.x, tid = threadIdx.x;
    float4 v = ((const float4*)(X + (size_t)row * 1024))[tid];
    float s  = v.x + v.y + v.z + v.w;
    float s2 = v.x*v.x + v.y*v.y + v.z*v.z + v.w*v.w;
    #pragma unroll
    for (int o = 16; o > 0; o >>= 1) {
        s  += __shfl_down_sync(0xffffffffu, s, o);
        s2 += __shfl_down_sync(0xffffffffu, s2, o);
    }
    int wid = tid >> 5;
    if ((tid & 31) == 0) { rs[wid] = s; rs[8 + wid] = s2; }
    __syncthreads();
    if (tid == 0) {
        float ts = 0.f, ts2 = 0.f;
        for (int w = 0; w < 8; w++) { ts += rs[w]; ts2 += rs[8 + w]; }
        float mu = ts * (1.f / 1024.f);
        float var = ts2 * (1.f / 1024.f) - mu * mu;
        rs[16] = mu;
        rs[17] = rsqrtf(var + 1e-6f);
    }
    __syncthreads();
    float mu = rs[16], rstd = rs[17];
    float4 gg = ((const float4*)g)[tid];
    float4 bb = ((const float4*)bta)[tid];
    float4 o;
    o.x = (v.x - mu) * rstd * gg.x + bb.x;
    o.y = (v.y - mu) * rstd * gg.y + bb.y;
    o.z = (v.z - mu) * rstd * gg.z + bb.z;
    o.w = (v.w - mu) * rstd * gg.w + bb.w;
    ((float4*)(Y + (size_t)row * 1024))[tid] = o;
    if (Yh) {
        __half2* yp = (__half2*)(Yh + (size_t)row * 1024);
        yp[2*tid]   = __floats2half2_rn(o.x, o.y);
        yp[2*tid+1] = __floats2half2_rn(o.z, o.w);
    }
}

// ---------------------------------------------------------------------------
extern "C" void kernel_launch(void* const* d_in, const int* in_sizes, int n_in,
                              void* d_out, int out_size)
{
    const float* q    = (const float*)d_in[0];
    const float* k    = (const float*)d_in[1];
    const float* v    = (const float*)d_in[2];
    const float* wq   = (const float*)d_in[3];
    const float* bq   = (const float*)d_in[4];
    const float* wk   = (const float*)d_in[5];
    const float* bk   = (const float*)d_in[6];
    const float* wv   = (const float*)d_in[7];
    const float* bv   = (const float*)d_in[8];
    const float* wfc  = (const float*)d_in[9];
    const float* bfc  = (const float*)d_in[10];
    const float* w1   = (const float*)d_in[11];
    const float* b1   = (const float*)d_in[12];
    const float* w2   = (const float*)d_in[13];
    const float* b2   = (const float*)d_in[14];
    const float* lng  = (const float*)d_in[15];
    const float* lnb  = (const float*)d_in[16];
    const float* relk = (const float*)d_in[17];
    const float* relv = (const float*)d_in[18];
    float* out = (float*)d_out;

    float *Qp, *Kp, *Vp, *T0p, *X1p;
    __half *qh, *kh, *vh, *AOh, *X1h, *Hh;
    __half *wqh, *wkh, *wvh, *wfh, *w1h, *w2h;
    cudaGetSymbolAddress((void**)&Qp,  g_Q);
    cudaGetSymbolAddress((void**)&Kp,  g_K);
    cudaGetSymbolAddress((void**)&Vp,  g_V);
    cudaGetSymbolAddress((void**)&T0p, g_T0);
    cudaGetSymbolAddress((void**)&X1p, g_X1);
    cudaGetSymbolAddress((void**)&qh,  g_qh);
    cudaGetSymbolAddress((void**)&kh,  g_kh);
    cudaGetSymbolAddress((void**)&vh,  g_vh);
    cudaGetSymbolAddress((void**)&AOh, g_AOh);
    cudaGetSymbolAddress((void**)&X1h, g_X1h);
    cudaGetSymbolAddress((void**)&Hh,  g_Hh);
    cudaGetSymbolAddress((void**)&wqh, g_WQH);
    cudaGetSymbolAddress((void**)&wkh, g_WKH);
    cudaGetSymbolAddress((void**)&wvh, g_WVH);
    cudaGetSymbolAddress((void**)&wfh, g_WFH);
    cudaGetSymbolAddress((void**)&w1h, g_W1H);
    cudaGetSymbolAddress((void**)&w2h, g_W2H);

    cudaFuncSetAttribute(attn_mma, cudaFuncAttributeMaxDynamicSharedMemorySize, ATTN_SMEM);
    cudaFuncSetAttribute(gemm_h,   cudaFuncAttributeMaxDynamicSharedMemorySize, GSMEMB);

    // pre-pass: half conversions (rn) + tiled weight packing
    const int MR = M_ROWS * DMODEL / 4;
    tohalf<<<(MR + 255) / 256, 256>>>(q, qh, MR);
    tohalf<<<(MR + 255) / 256, 256>>>(k, kh, MR);
    tohalf<<<(MR + 255) / 256, 256>>>(v, vh, MR);
    prep_weight<<<dim3(1024/128, 1024/32), 256>>>(wq,  wqh, 1024, 1024);
    prep_weight<<<dim3(1024/128, 1024/32), 256>>>(wk,  wkh, 1024, 1024);
    prep_weight<<<dim3(1024/128, 1024/32), 256>>>(wv,  wvh, 1024, 1024);
    prep_weight<<<dim3(1024/128, 1024/32), 256>>>(wfc, wfh, 1024, 1024);
    prep_weight<<<dim3(4096/128, 1024/32), 256>>>(w1,  w1h, 1024, 4096);
    prep_weight<<<dim3(1024/128, 4096/32), 256>>>(w2,  w2h, 4096, 1024);

    dim3 blk(256);
    dim3 g1024(1024 / 128, 8192 / 128);
    dim3 g4096(4096 / 128, 8192 / 128);

    gemm_h<<<g1024, blk, GSMEMB>>>(qh, wqh, bq, nullptr, Qp, nullptr, 1024, 1024, 0);
    gemm_h<<<g1024, blk, GSMEMB>>>(kh, wkh, bk, nullptr, Kp, nullptr, 1024, 1024, 0);
    gemm_h<<<g1024, blk, GSMEMB>>>(vh, wvh, bv, nullptr, Vp, nullptr, 1024, 1024, 0);

    attn_mma<<<dim3(16, NHEAD, 8), blk, ATTN_SMEM>>>(Qp, Kp, Vp, relk, relv, AOh);

    gemm_h<<<g1024, blk, GSMEMB>>>(AOh, wfh, bfc, q, T0p, nullptr, 1024, 1024, 0);
    ln_kernel<<<8192, 256>>>(T0p, lng, lnb, X1p, X1h);

    gemm_h<<<g4096, blk, GSMEMB>>>(X1h, w1h, b1, nullptr, nullptr, Hh, 4096, 1024, 1);
    gemm_h<<<g1024, blk, GSMEMB>>>(Hh, w2h, b2, X1p, T0p, nullptr, 1024, 4096, 0);
    ln_kernel<<<8192, 256>>>(T0p, lng, lnb, out, nullptr);
}